// round 13
// baseline (speedup 1.0000x reference)
#include <cuda_runtime.h>
#include <cuda_bf16.h>
#include <math.h>

#define D_    256
#define NB    64
#define SEQ   1024
#define EPSV  1e-10f
#define NIT   12
#define NROUNDS 6          // multisection rounds, 9x contraction each

// closed-form constants
#define ALPHA     0.32768f        // (1-2*ETA)^5
#define ALPHA2_64 0.0016777216f   // ALPHA^2 / 64
#define ALPHA_8   0.04096f        // ALPHA / 8
#define BETA      0.59049f        // (1-ETA)^5
#define OMBETA    0.40951f        // 1 - BETA

#define BAR128() asm volatile("bar.sync 1, 128;" ::: "memory")

// ---------------- device scratch (no allocations allowed) ----------------
__device__ float g_D0[NB * D_];         // deviations
__device__ float g_Gg[NB * NB];         // Gram matrix
__device__ float g_Wg[NB * NB];         // eigenvectors of G (columns, ascending)
__device__ float g_UT[NB * D_];         // UT[k][d]: eigvec k of A (63 used)
__device__ float g_poles[NB];           // poles[0]=0, poles[1..63] ascending
__device__ float g_trA;                 // sum of kept poles
__device__ float g_M[SEQ * D_];         // m_t per step

// ------ 1) fused scan (32 blocks) + gram (64 blocks)  <<<96,256>>> -------
__global__ void k_scan_gram(const int* __restrict__ tokens,
                            const float* __restrict__ embed,
                            const float* __restrict__ bubbles,
                            const float* __restrict__ mdecay) {
    __shared__ float rowi[D_];
    __shared__ float bmsh[D_];
    __shared__ int   tk[128];
    int t = threadIdx.x;

    if (blockIdx.x < 64) {
        // ---- gram block i: G[i][*] = (a^2/64) D0_i . D0_j ----
        int i = blockIdx.x;
        float s = 0.f;
#pragma unroll 8
        for (int r = 0; r < NB; r++) s += bubbles[r * D_ + t];
        float bm = s * (1.f / NB);
        float v = bubbles[i * D_ + t] - bm;
        rowi[t] = v;
        bmsh[t] = bm;
        g_D0[i * D_ + t] = v;
        __syncthreads();

        int lane = t & 31, w = t >> 5;
#pragma unroll
        for (int it = 0; it < 8; it++) {
            int j = w * 8 + it;
            const float* bj = bubbles + j * D_;
            float acc = 0.f;
#pragma unroll
            for (int m = 0; m < 8; m++) {
                int d = lane + 32 * m;
                acc += rowi[d] * (bj[d] - bmsh[d]);
            }
#pragma unroll
            for (int o = 16; o > 0; o >>= 1)
                acc += __shfl_down_sync(0xFFFFFFFFu, acc, o);
            if (lane == 0) g_Gg[i * NB + j] = acc * ALPHA2_64;
        }
    } else {
        // ---- scan block: contraction a ~ 0.778, a^96 ~ 3e-11 warmup ----
        int c = blockIdx.x - 64, d = t;
        float s0 = 0.f, s1 = 0.f;
#pragma unroll 8
        for (int r = 0; r < NB; r += 2) {
            s0 += bubbles[r * D_ + d];
            s1 += bubbles[(r + 1) * D_ + d];
        }
        float cb = BETA * (s0 + s1) * (1.f / NB);
        float decay = 1.f / (1.f + expf(-mdecay[0]));
        float omdecay = 1.f - decay;

        int tout = c * 32;
        int tstart = tout - 96; if (tstart < 0) tstart = 0;
        int tend = tout + 32;
        int nwin = tend - tstart;
        if (d < nwin) tk[d] = tokens[tstart + d];
        __syncthreads();

        float mm = 0.f;
        float xs[8];
#pragma unroll
        for (int j = 0; j < 8; j++) xs[j] = embed[(long)tk[j] * D_ + d];
        for (int t0 = tstart; t0 < tend; t0 += 8) {
#pragma unroll
            for (int j = 0; j < 8; j++) {
                int tt = t0 + j;
                float x = xs[j];
                int tn = t0 + 8 + j;
                if (tn < tend) xs[j] = embed[(long)tk[tn - tstart] * D_ + d];
                float m = cb + OMBETA * (x + decay * mm);
                if (tt >= tout) g_M[tt * D_ + d] = m;
                mm = decay * mm + omdecay * m;
            }
        }
    }
}

// ------ 2) fused eigensolver  <<<1, 1024, 66560>>> -----------------------
// phase T: 128-thread split-row Householder tridiag (32 regs/thread, no spill)
// phase S: multisection Sturm (512 threads)
// phase I: inverse iteration with stored reciprocals (64 threads)
// phase B: back-transform (1024 threads)
__global__ void __launch_bounds__(1024, 1) k_eigvec() {
    extern __shared__ float sm[];
    float* E  = sm;                   // 64x65 eigvec columns
    float* DD = sm + 4160;            // invit scratch: reciprocal pivots
    float* YY = sm + 8320;            // invit scratch
    float* V  = sm + 12480;           // reflectors [k][r], pitch 65

    __shared__ float diag[64], off[64], b2[64], eig[64], tauv[64];
    __shared__ float xsh[64], vsh[64], wsh[64], psh[64], phalf[128];
    __shared__ float red[32];
    __shared__ int   oflag[64];
    __shared__ float sc_lo, sc_hi;

    int tid = threadIdx.x, lane = tid & 31, warp = tid >> 5;

    // ---- phase T: tridiagonalization (threads 0..127) ----
    if (tid < 128) {
        int h = tid >> 6, r = tid & 63;   // h: column half, r: row
        float rcol[32];
#pragma unroll
        for (int c = 0; c < 32; c++) rcol[c] = g_Gg[r * NB + h * 32 + c];

#pragma unroll 1
        for (int k = 0; k < 62; k++) {
            int n0 = k + 1;
            // publish current column k
            if (h == (k >> 5)) xsh[r] = rcol[k & 31];
            BAR128();
            // norm over rows >= n0 (threads with h==0)
            if (h == 0) {
                float xm = (r >= n0) ? xsh[r] : 0.f;
                float s = xm * xm;
#pragma unroll
                for (int o = 16; o > 0; o >>= 1)
                    s += __shfl_xor_sync(0xFFFFFFFFu, s, o);
                if (lane == 0) red[warp] = s;
            }
            BAR128();
            float sum = red[0] + red[1];
            float x0 = xsh[n0];
            float sigma = sqrtf(sum);
            float sgn = (x0 >= 0.f) ? 1.f : -1.f;
            float tau = (sum > 1e-30f)
                      ? __fdividef(1.f, sigma * (sigma + fabsf(x0))) : 0.f;
            if (h == 0) {
                float v = (r == n0) ? x0 + sgn * sigma
                                    : ((r > n0) ? xsh[r] : 0.f);
                vsh[r] = v;
                V[k * 65 + r] = v;
                if (r == 0) { off[k] = -sgn * sigma; tauv[k] = tau; }
            }
            BAR128();
            // matvec partial: this thread's 32 columns
            float pp = 0.f;
#pragma unroll
            for (int c = 0; c < 32; c++) pp += rcol[c] * vsh[h * 32 + c];
            phalf[h * 64 + r] = pp;
            BAR128();
            if (h == 0) {
                float p = tau * (phalf[r] + phalf[64 + r]);
                psh[r] = p;
                float pv = p * vsh[r];
#pragma unroll
                for (int o = 16; o > 0; o >>= 1)
                    pv += __shfl_xor_sync(0xFFFFFFFFu, pv, o);
                if (lane == 0) red[warp] = pv;
            }
            BAR128();
            float K = 0.5f * tau * (red[0] + red[1]);
            if (h == 0) wsh[r] = (r >= n0) ? (psh[r] - K * vsh[r]) : 0.f;
            BAR128();
            // rank-2 update on this thread's 32 columns
            float vr = vsh[r], wr = wsh[r];
#pragma unroll
            for (int c = 0; c < 32; c++)
                rcol[c] -= vr * wsh[h * 32 + c] + wr * vsh[h * 32 + c];
        }

        // extract diagonal / last off-diagonal
        if (h == (r >> 5)) diag[r] = rcol[r & 31];
        if (h == 1 && r == 63) off[62] = rcol[30];
        if (tid == 0) off[63] = 0.f;
    }
    __syncthreads();   // all 1024 threads join

    if (tid < 63) b2[tid] = off[tid] * off[tid];
    if (tid == 0) {
        float lo = 1e30f, hi = -1e30f;
        for (int i = 0; i < 64; i++) {
            float om = (i > 0) ? fabsf(off[i - 1]) : 0.f;
            float op = (i < 63) ? fabsf(off[i]) : 0.f;
            lo = fminf(lo, diag[i] - om - op);
            hi = fmaxf(hi, diag[i] + om + op);
        }
        float mg = 1e-6f * fmaxf(fabsf(lo), fabsf(hi)) + 1e-30f;
        sc_lo = lo - mg; sc_hi = hi + mg;
    }
    __syncthreads();

    // ---- phase S: multisection Sturm, 8 threads per eigenvalue ----
    if (tid < 512) {
        int i = tid >> 3, s8 = tid & 7;
        float lo = sc_lo, hi = sc_hi;
        for (int round = 0; round < NROUNDS; round++) {
            float step = (hi - lo) * (1.f / 9.f);
            float mid = lo + step * (float)(s8 + 1);
            float d = diag[0] - mid;
            int cnt = (d < 0.f);
            for (int j = 1; j < 64; j++) {
                float dg = (fabsf(d) < 1e-25f) ? -1e-25f : d;
                d = (diag[j] - mid) - __fdividef(b2[j - 1], dg);
                cnt += (d < 0.f);
            }
            unsigned bal = __ballot_sync(0xFFFFFFFFu, cnt <= i);
            unsigned bits = (bal >> (lane & 24)) & 0xFFu;
            int p = __popc(bits);
            lo = lo + step * (float)p;
            hi = lo + step;
        }
        if (s8 == 0) eig[i] = 0.5f * (lo + hi);
    }
    __syncthreads();

    // ---- phase I: inverse iteration (reciprocal pivots cached in DD) ----
    if (tid < 64) {
        int i = tid;
        float scale = fmaxf(fabsf(sc_hi), fabsf(sc_lo));
        float lam = eig[i] + scale * 2e-6f;
        unsigned h = (unsigned)(i * 2654435761u) ^ 0x9E3779B9u;
        for (int j = 0; j < 64; j++) {
            h = h * 1664525u + 1013904223u;
            E[j * 65 + i] = 1.f + (float)(h >> 16) * 1.52587890625e-05f;
        }
        for (int iter = 0; iter < 3; iter++) {
            // forward elimination; DD holds reciprocal pivots
            float d0 = diag[0] - lam;
            d0 = (fabsf(d0) < 1e-20f) ? copysignf(1e-20f, d0) : d0;
            float rc;
            asm("rcp.approx.f32 %0, %1;" : "=f"(rc) : "f"(d0));
            DD[i * 65 + 0] = rc;
            float yprev = E[0 * 65 + i];
            YY[i * 65 + 0] = yprev;
            for (int j = 1; j < 64; j++) {
                float m = off[j - 1] * rc;
                float dcur = (diag[j] - lam) - m * off[j - 1];
                dcur = (fabsf(dcur) < 1e-20f) ? copysignf(1e-20f, dcur) : dcur;
                float rcn;
                asm("rcp.approx.f32 %0, %1;" : "=f"(rcn) : "f"(dcur));
                float ycur = E[j * 65 + i] - m * yprev;
                DD[i * 65 + j] = rcn;
                YY[i * 65 + j] = ycur;
                rc = rcn; yprev = ycur;
            }
            // back substitution: chain = FMA + FMUL (loads prefetchable)
            float vj = yprev * rc;
            E[63 * 65 + i] = vj;
            float nrm = vj * vj;
            for (int j = 62; j >= 0; j--) {
                vj = (YY[i * 65 + j] - off[j] * vj) * DD[i * 65 + j];
                E[j * 65 + i] = vj;
                nrm += vj * vj;
            }
            float inv = rsqrtf(nrm);
            for (int j = 0; j < 64; j++) E[j * 65 + i] *= inv;
        }
    }
    __syncthreads();

    // ---- gap-flagged neighbor re-orthogonalization ----
    if (tid < 64) {
        float scale = fmaxf(fabsf(eig[63]), fabsf(eig[0]));
        oflag[tid] = (tid > 0) && (eig[tid] - eig[tid - 1] < 1e-3f * scale);
    }
    __syncthreads();
    for (int i = 1; i < 64; i++) {
        if (!oflag[i]) continue;
        float pr = (tid < 64) ? E[tid * 65 + i] * E[tid * 65 + i - 1] : 0.f;
#pragma unroll
        for (int o = 16; o > 0; o >>= 1)
            pr += __shfl_down_sync(0xFFFFFFFFu, pr, o);
        if (lane == 0 && tid < 64) red[warp] = pr;
        __syncthreads();
        float dot = red[0] + red[1];
        float nv = 0.f;
        if (tid < 64) {
            E[tid * 65 + i] -= dot * E[tid * 65 + i - 1];
            nv = E[tid * 65 + i] * E[tid * 65 + i];
        }
#pragma unroll
        for (int o = 16; o > 0; o >>= 1)
            nv += __shfl_down_sync(0xFFFFFFFFu, nv, o);
        if (lane == 0 && tid < 64) red[warp] = nv;
        __syncthreads();
        float sc = rsqrtf(red[0] + red[1] + 1e-30f);
        if (tid < 64) E[tid * 65 + i] *= sc;
        __syncthreads();
    }

    // ---- phase B: back-transform, reflectors k = 61..0 (cols indep) ----
    {
        int col = tid >> 4, sub = tid & 15;
        for (int k = 61; k >= 0; k--) {
            int n0 = k + 1, n2 = 63 - k;
            float tau = tauv[k];
            float acc = 0.f;
            for (int r = sub; r < n2; r += 16)
                acc += V[k * 65 + n0 + r] * E[(n0 + r) * 65 + col];
#pragma unroll
            for (int o = 8; o > 0; o >>= 1)
                acc += __shfl_xor_sync(0xFFFFFFFFu, acc, o, 16);
            float w = tau * acc;
            for (int r = sub; r < n2; r += 16)
                E[(n0 + r) * 65 + col] -= w * V[k * 65 + n0 + r];
        }
    }
    __syncthreads();

    if (tid == 0) {
        g_poles[0] = 0.f;
        float s = 0.f;
        for (int k = 1; k < 64; k++) {
            float p = fmaxf(eig[k], 1e-12f);
            g_poles[k] = p;
            s += p;
        }
        g_trA = s;
    }
    for (int e = tid; e < NB * NB; e += 1024)
        g_Wg[e] = E[(e >> 6) * 65 + (e & 63)];
}

// ------ 3) build U^T  <<<63,256>>>  (full unroll -> deep MLP) ------------
__global__ void k_buildU() {
    __shared__ float wcol[NB];
    int k = blockIdx.x, d = threadIdx.x;
    if (d < NB) wcol[d] = g_Wg[d * NB + (k + 1)];   // ascending columns
    __syncthreads();
    float acc = 0.f;
#pragma unroll
    for (int i = 0; i < NB; i++) acc += __ldg(&g_D0[i * D_ + d]) * wcol[i];
    float lam = g_poles[k + 1];
    g_UT[k * D_ + d] = acc * ALPHA_8 * rsqrtf(fmaxf(lam, 1e-20f));
}

// ------ 4) fused weights + secular, 4 timesteps/block <<<256,256>>> ------
__global__ void k_wsec(float* __restrict__ out) {
    __shared__ float  smv[4][D_];
    __shared__ float  zsh[4][64];
    __shared__ float  redp[4][8];
    __shared__ float2 dw[4][NB];
    __shared__ float  vals[4][NB];
    __shared__ float  msqs[4];
    int bid = blockIdx.x, tid = threadIdx.x;
    int warp = tid >> 5, lane = tid & 31;
    int t0 = bid * 4;

    float mv[4];
#pragma unroll
    for (int q = 0; q < 4; q++) {
        mv[q] = g_M[(t0 + q) * D_ + tid];
        smv[q][tid] = mv[q];
    }
#pragma unroll
    for (int q = 0; q < 4; q++) {
        float p = mv[q] * mv[q];
#pragma unroll
        for (int o = 16; o > 0; o >>= 1)
            p += __shfl_down_sync(0xFFFFFFFFu, p, o);
        if (lane == 0) redp[q][warp] = p;
    }
    __syncthreads();

    // z_k = U_k . m  (warp-per-k; UT row loaded once, reused for 4 t's)
#pragma unroll
    for (int it = 0; it < 8; it++) {
        int k = warp * 8 + it;
        if (k < 63) {
            float a0 = 0.f, a1 = 0.f, a2 = 0.f, a3 = 0.f;
#pragma unroll
            for (int j = 0; j < 8; j++) {
                int d = lane + 32 * j;
                float u = g_UT[k * D_ + d];
                a0 += u * smv[0][d];
                a1 += u * smv[1][d];
                a2 += u * smv[2][d];
                a3 += u * smv[3][d];
            }
#pragma unroll
            for (int o = 16; o > 0; o >>= 1) {
                a0 += __shfl_down_sync(0xFFFFFFFFu, a0, o);
                a1 += __shfl_down_sync(0xFFFFFFFFu, a1, o);
                a2 += __shfl_down_sync(0xFFFFFFFFu, a2, o);
                a3 += __shfl_down_sync(0xFFFFFFFFu, a3, o);
            }
            if (lane == 0) {
                zsh[0][k] = a0; zsh[1][k] = a1;
                zsh[2][k] = a2; zsh[3][k] = a3;
            }
        }
    }
    __syncthreads();

    // weights: thread (sel*64 + i) fills dw[sel][i]
    {
        int sel = tid >> 6, i = tid & 63;
        if (i == 0) {
            float msq = 0.f;
#pragma unroll
            for (int w = 0; w < 8; w++) msq += redp[sel][w];
            float sz = 0.f;
            for (int k = 0; k < 63; k++) sz += zsh[sel][k] * zsh[sel][k];
            dw[sel][0] = make_float2(g_poles[0], fmaxf(msq - sz, 0.f));
            msqs[sel] = msq;
        } else {
            float z = zsh[sel][i - 1];
            dw[sel][i] = make_float2(g_poles[i], z * z);
        }
    }
    __syncthreads();

    int sel = tid >> 6, i = tid & 63;
    float S = 0.f;
#pragma unroll 8
    for (int k = 0; k < NB; k++) S += dw[sel][k].y;

    float lo = dw[sel][i].x;
    float hi = (i < 63) ? dw[sel][i + 1].x : dw[sel][63].x + S;
    float lam = 0.5f * (lo + hi);

    for (int it = 0; it < NIT; it++) {
        float f = 1.f, fp = 0.f;
#pragma unroll 8
        for (int k = 0; k < NB; k++) {
            float2 p = dw[sel][k];
            float diff = p.x - lam;
            float rc;
            asm("rcp.approx.f32 %0, %1;" : "=f"(rc) : "f"(diff));
            float term = p.y * rc;
            f  += term;
            fp += term * rc;
        }
        if (f > 0.f) hi = lam; else lo = lam;
        float ln = lam - __fdividef(f, fp);
        lam = (ln > lo && ln < hi) ? ln : 0.5f * (lo + hi);
    }

    float tr = msqs[sel] + g_trA;
    float v = fmaxf(__fdividef(lam, tr), EPSV);
    vals[sel][i] = v;
    __syncthreads();

    float ssum = 192.f * EPSV;
#pragma unroll 8
    for (int k = 0; k < NB; k++) ssum += vals[sel][k];
    float inv = __frcp_rn(ssum);

    float* o = out + (long)(t0 + sel) * D_;
    float ev = EPSV * inv;
    o[i]        = ev;               // positions   0..63  (zero eigs)
    o[i + 64]   = ev;               // positions  64..127
    o[i + 128]  = ev;               // positions 128..191
    o[i + 192]  = vals[sel][i] * inv;  // positions 192..255 (roots, ascending)
}

// ---------------- launcher ----------------
extern "C" void kernel_launch(void* const* d_in, const int* in_sizes, int n_in,
                              void* d_out, int out_size) {
    const int*   tokens = (const int*)d_in[0];
    const float* embed  = (const float*)d_in[1];
    const float* bubbles= (const float*)d_in[2];
    const float* mdecay = (const float*)d_in[3];
    float* out = (float*)d_out;

    cudaFuncSetAttribute(k_eigvec, cudaFuncAttributeMaxDynamicSharedMemorySize,
                         66560);

    k_scan_gram<<<96, 256>>>(tokens, embed, bubbles, mdecay);
    k_eigvec   <<<1, 1024, 66560>>>();
    k_buildU   <<<63, 256>>>();
    k_wsec     <<<256, 256>>>(out);
    (void)in_sizes; (void)n_in; (void)out_size;
}

// round 14
// speedup vs baseline: 1.0152x; 1.0152x over previous
#include <cuda_runtime.h>
#include <cuda_bf16.h>
#include <math.h>

#define D_    256
#define NB    64
#define SEQ   1024
#define EPSV  1e-10f
#define NIT   12
#define NROUNDS 6          // multisection rounds, 9x contraction each

// closed-form constants
#define ALPHA     0.32768f        // (1-2*ETA)^5
#define ALPHA2_64 0.0016777216f   // ALPHA^2 / 64
#define ALPHA_8   0.04096f        // ALPHA / 8
#define BETA      0.59049f        // (1-ETA)^5
#define OMBETA    0.40951f        // 1 - BETA

// ---------------- device scratch (no allocations allowed) ----------------
__device__ float g_D0[NB * D_];         // deviations
__device__ float g_Gg[NB * NB];         // Gram matrix
__device__ float g_V[62 * NB];          // Householder reflectors
__device__ float g_tau[64];             // reflector taus
__device__ float g_diag[NB];            // tridiag diagonal
__device__ float g_off[NB];             // tridiag off-diagonal
__device__ float g_Wg[NB * NB];         // eigenvectors of G (columns, ascending)
__device__ float g_UT[NB * D_];         // UT[k][d]: eigvec k of A (63 used)
__device__ float g_poles[NB];           // poles[0]=0, poles[1..63] ascending
__device__ float g_trA;                 // sum of kept poles
__device__ float g_M[SEQ * D_];         // m_t per step

// ------ 1) fused scan (32 blocks) + gram (64 blocks)  <<<96,256>>> -------
__global__ void k_scan_gram(const int* __restrict__ tokens,
                            const float* __restrict__ embed,
                            const float* __restrict__ bubbles,
                            const float* __restrict__ mdecay) {
    __shared__ float rowi[D_];
    __shared__ float bmsh[D_];
    __shared__ int   tk[128];
    int t = threadIdx.x;

    if (blockIdx.x < 64) {
        // ---- gram block i: G[i][*] = (a^2/64) D0_i . D0_j ----
        int i = blockIdx.x;
        float s = 0.f;
#pragma unroll 8
        for (int r = 0; r < NB; r++) s += bubbles[r * D_ + t];
        float bm = s * (1.f / NB);
        float v = bubbles[i * D_ + t] - bm;
        rowi[t] = v;
        bmsh[t] = bm;
        g_D0[i * D_ + t] = v;
        __syncthreads();

        int lane = t & 31, w = t >> 5;
#pragma unroll
        for (int it = 0; it < 8; it++) {
            int j = w * 8 + it;
            const float* bj = bubbles + j * D_;
            float acc = 0.f;
#pragma unroll
            for (int m = 0; m < 8; m++) {
                int d = lane + 32 * m;
                acc += rowi[d] * (bj[d] - bmsh[d]);
            }
#pragma unroll
            for (int o = 16; o > 0; o >>= 1)
                acc += __shfl_down_sync(0xFFFFFFFFu, acc, o);
            if (lane == 0) g_Gg[i * NB + j] = acc * ALPHA2_64;
        }
    } else {
        // ---- scan block: contraction a ~ 0.778, a^96 ~ 3e-11 warmup ----
        int c = blockIdx.x - 64, d = t;
        float s0 = 0.f, s1 = 0.f;
#pragma unroll 8
        for (int r = 0; r < NB; r += 2) {
            s0 += bubbles[r * D_ + d];
            s1 += bubbles[(r + 1) * D_ + d];
        }
        float cb = BETA * (s0 + s1) * (1.f / NB);
        float decay = 1.f / (1.f + expf(-mdecay[0]));
        float omdecay = 1.f - decay;

        int tout = c * 32;
        int tstart = tout - 96; if (tstart < 0) tstart = 0;
        int tend = tout + 32;
        int nwin = tend - tstart;
        if (d < nwin) tk[d] = tokens[tstart + d];
        __syncthreads();

        float mm = 0.f;
        float xs[8];
#pragma unroll
        for (int j = 0; j < 8; j++) xs[j] = embed[(long)tk[j] * D_ + d];
        for (int t0 = tstart; t0 < tend; t0 += 8) {
#pragma unroll
            for (int j = 0; j < 8; j++) {
                int tt = t0 + j;
                float x = xs[j];
                int tn = t0 + 8 + j;
                if (tn < tend) xs[j] = embed[(long)tk[tn - tstart] * D_ + d];
                float m = cb + OMBETA * (x + decay * mm);
                if (tt >= tout) g_M[tt * D_ + d] = m;
                mm = decay * mm + omdecay * m;
            }
        }
    }
}

// ------ 2) register-resident Householder tridiagonalization <<<1,64>>> ---
__global__ void __launch_bounds__(64) k_tridiag() {
    __shared__ float vsh[NB], wsh[NB], red2[2];
    __shared__ float x0sh;
    float row[NB];
    int r = threadIdx.x, lane = r & 31, warp = r >> 5;

#pragma unroll
    for (int c = 0; c < NB; c++) row[c] = g_Gg[r * NB + c];
    float x = row[0];

#pragma unroll 1
    for (int k = 0; k < 62; k++) {
        int n0 = k + 1;
        float xm = (r >= n0) ? x : 0.f;
        float s = xm * xm;
#pragma unroll
        for (int o = 16; o > 0; o >>= 1) s += __shfl_xor_sync(0xFFFFFFFFu, s, o);
        if (lane == 0) red2[warp] = s;
        if (r == n0) x0sh = xm;
        __syncthreads();
        float sum = red2[0] + red2[1];
        float x0 = x0sh;
        float sigma = sqrtf(sum);
        float sgn = (x0 >= 0.f) ? 1.f : -1.f;
        float tau = (sum > 1e-30f)
                  ? __fdividef(1.f, sigma * (sigma + fabsf(x0))) : 0.f;
        if (r == 0) { g_off[k] = -sgn * sigma; g_tau[k] = tau; }
        float v = (r == n0) ? x0 + sgn * sigma : xm;   // xm==0 for r<n0
        vsh[r] = v;
        g_V[k * NB + r] = v;
        __syncthreads();
        float a0 = 0.f, a1 = 0.f, a2 = 0.f, a3 = 0.f;
#pragma unroll
        for (int c = 0; c < NB; c += 4) {
            a0 += row[c]     * vsh[c];
            a1 += row[c + 1] * vsh[c + 1];
            a2 += row[c + 2] * vsh[c + 2];
            a3 += row[c + 3] * vsh[c + 3];
        }
        float p = tau * ((a0 + a1) + (a2 + a3));
        float pv = p * v;
#pragma unroll
        for (int o = 16; o > 0; o >>= 1) pv += __shfl_xor_sync(0xFFFFFFFFu, pv, o);
        if (lane == 0) red2[warp] = pv;
        __syncthreads();
        float K = 0.5f * tau * (red2[0] + red2[1]);
        float w = (r >= n0) ? (p - K * v) : 0.f;
        wsh[r] = w;
        __syncthreads();
        float xn = x;
#pragma unroll
        for (int c = 0; c < NB; c++) {
            float nv = row[c] - v * wsh[c] - w * vsh[c];
            row[c] = nv;
            if (c == n0) xn = nv;
        }
        x = xn;
    }

    float dg = 0.f;
#pragma unroll
    for (int c = 0; c < NB; c++) if (c == r) dg = row[c];
    g_diag[r] = dg;
    if (r == 63) g_off[62] = row[62];
    if (r == 0)  g_off[63] = 0.f;
}

// ------ 3) eigvecs: multisection Sturm + invit + backtransform -----------
__global__ void k_eigvec() {          // <<<1, 1024, 66560>>>
    extern __shared__ float sm[];
    float* E  = sm;                   // 64x65 eigvec columns
    float* DD = sm + 4160;            // invit scratch: reciprocal pivots
    float* YY = sm + 8320;            // invit scratch
    float* V  = sm + 12480;           // reflectors [k][r], pitch 65

    __shared__ float diag[64], off[64], b2[64], eig[64], tauv[64];
    __shared__ float red[32];
    __shared__ int   oflag[64];
    __shared__ float sc_lo, sc_hi;

    int tid = threadIdx.x, lane = tid & 31, warp = tid >> 5;

    if (tid < 64) { diag[tid] = g_diag[tid]; off[tid] = g_off[tid]; }
    if (tid < 62) tauv[tid] = g_tau[tid];
    for (int e = tid; e < 62 * NB; e += 1024)
        V[(e >> 6) * 65 + (e & 63)] = g_V[e];
    __syncthreads();
    if (tid < 63) b2[tid] = off[tid] * off[tid];
    if (tid == 0) {
        float lo = 1e30f, hi = -1e30f;
        for (int i = 0; i < 64; i++) {
            float om = (i > 0) ? fabsf(off[i - 1]) : 0.f;
            float op = (i < 63) ? fabsf(off[i]) : 0.f;
            lo = fminf(lo, diag[i] - om - op);
            hi = fmaxf(hi, diag[i] + om + op);
        }
        float mg = 1e-6f * fmaxf(fabsf(lo), fabsf(hi)) + 1e-30f;
        sc_lo = lo - mg; sc_hi = hi + mg;
    }
    __syncthreads();

    // ---- multisection Sturm: 8 threads per eigenvalue ----
    if (tid < 512) {
        int i = tid >> 3, s8 = tid & 7;
        float lo = sc_lo, hi = sc_hi;
        for (int round = 0; round < NROUNDS; round++) {
            float step = (hi - lo) * (1.f / 9.f);
            float mid = lo + step * (float)(s8 + 1);
            float d = diag[0] - mid;
            int cnt = (d < 0.f);
            for (int j = 1; j < 64; j++) {
                float dg = (fabsf(d) < 1e-25f) ? -1e-25f : d;
                d = (diag[j] - mid) - __fdividef(b2[j - 1], dg);
                cnt += (d < 0.f);
            }
            unsigned bal = __ballot_sync(0xFFFFFFFFu, cnt <= i);
            unsigned bits = (bal >> (lane & 24)) & 0xFFu;
            int p = __popc(bits);
            lo = lo + step * (float)p;
            hi = lo + step;
        }
        if (s8 == 0) eig[i] = 0.5f * (lo + hi);
    }
    __syncthreads();

    // ---- inverse iteration (reciprocal pivots cached in DD) ----
    if (tid < 64) {
        int i = tid;
        float scale = fmaxf(fabsf(sc_hi), fabsf(sc_lo));
        float lam = eig[i] + scale * 2e-6f;
        unsigned h = (unsigned)(i * 2654435761u) ^ 0x9E3779B9u;
        for (int j = 0; j < 64; j++) {
            h = h * 1664525u + 1013904223u;
            E[j * 65 + i] = 1.f + (float)(h >> 16) * 1.52587890625e-05f;
        }
        for (int iter = 0; iter < 3; iter++) {
            float d0 = diag[0] - lam;
            d0 = (fabsf(d0) < 1e-20f) ? copysignf(1e-20f, d0) : d0;
            float rc;
            asm("rcp.approx.f32 %0, %1;" : "=f"(rc) : "f"(d0));
            DD[i * 65 + 0] = rc;
            float yprev = E[0 * 65 + i];
            YY[i * 65 + 0] = yprev;
            for (int j = 1; j < 64; j++) {
                float m = off[j - 1] * rc;
                float dcur = (diag[j] - lam) - m * off[j - 1];
                dcur = (fabsf(dcur) < 1e-20f) ? copysignf(1e-20f, dcur) : dcur;
                float rcn;
                asm("rcp.approx.f32 %0, %1;" : "=f"(rcn) : "f"(dcur));
                float ycur = E[j * 65 + i] - m * yprev;
                DD[i * 65 + j] = rcn;
                YY[i * 65 + j] = ycur;
                rc = rcn; yprev = ycur;
            }
            float vj = yprev * rc;
            E[63 * 65 + i] = vj;
            float nrm = vj * vj;
            for (int j = 62; j >= 0; j--) {
                vj = (YY[i * 65 + j] - off[j] * vj) * DD[i * 65 + j];
                E[j * 65 + i] = vj;
                nrm += vj * vj;
            }
            float inv = rsqrtf(nrm);
            for (int j = 0; j < 64; j++) E[j * 65 + i] *= inv;
        }
    }
    __syncthreads();

    // ---- gap-flagged neighbor re-orthogonalization ----
    if (tid < 64) {
        float scale = fmaxf(fabsf(eig[63]), fabsf(eig[0]));
        oflag[tid] = (tid > 0) && (eig[tid] - eig[tid - 1] < 1e-3f * scale);
    }
    __syncthreads();
    for (int i = 1; i < 64; i++) {
        if (!oflag[i]) continue;
        float pr = (tid < 64) ? E[tid * 65 + i] * E[tid * 65 + i - 1] : 0.f;
#pragma unroll
        for (int o = 16; o > 0; o >>= 1)
            pr += __shfl_down_sync(0xFFFFFFFFu, pr, o);
        if (lane == 0 && tid < 64) red[warp] = pr;
        __syncthreads();
        float dot = red[0] + red[1];
        float nv = 0.f;
        if (tid < 64) {
            E[tid * 65 + i] -= dot * E[tid * 65 + i - 1];
            nv = E[tid * 65 + i] * E[tid * 65 + i];
        }
#pragma unroll
        for (int o = 16; o > 0; o >>= 1)
            nv += __shfl_down_sync(0xFFFFFFFFu, nv, o);
        if (lane == 0 && tid < 64) red[warp] = nv;
        __syncthreads();
        float sc = rsqrtf(red[0] + red[1] + 1e-30f);
        if (tid < 64) E[tid * 65 + i] *= sc;
        __syncthreads();
    }

    // ---- back-transform: apply reflectors k = 61..0 (cols independent) --
    {
        int col = tid >> 4, sub = tid & 15;
        for (int k = 61; k >= 0; k--) {
            int n0 = k + 1, n2 = 63 - k;
            float tau = tauv[k];
            float acc = 0.f;
            for (int r = sub; r < n2; r += 16)
                acc += V[k * 65 + n0 + r] * E[(n0 + r) * 65 + col];
#pragma unroll
            for (int o = 8; o > 0; o >>= 1)
                acc += __shfl_xor_sync(0xFFFFFFFFu, acc, o, 16);
            float w = tau * acc;
            for (int r = sub; r < n2; r += 16)
                E[(n0 + r) * 65 + col] -= w * V[k * 65 + n0 + r];
        }
    }
    __syncthreads();

    if (tid == 0) {
        g_poles[0] = 0.f;
        float s = 0.f;
        for (int k = 1; k < 64; k++) {
            float p = fmaxf(eig[k], 1e-12f);
            g_poles[k] = p;
            s += p;
        }
        g_trA = s;
    }
    for (int e = tid; e < NB * NB; e += 1024)
        g_Wg[e] = E[(e >> 6) * 65 + (e & 63)];
}

// ------ 4) build U^T  <<<63,256>>>  (full unroll -> deep MLP) ------------
__global__ void k_buildU() {
    __shared__ float wcol[NB];
    int k = blockIdx.x, d = threadIdx.x;
    if (d < NB) wcol[d] = g_Wg[d * NB + (k + 1)];   // ascending columns
    __syncthreads();
    float acc = 0.f;
#pragma unroll
    for (int i = 0; i < NB; i++) acc += __ldg(&g_D0[i * D_ + d]) * wcol[i];
    float lam = g_poles[k + 1];
    g_UT[k * D_ + d] = acc * ALPHA_8 * rsqrtf(fmaxf(lam, 1e-20f));
}

// ------ 5) fused weights + secular, 4 timesteps/block <<<256,256>>> ------
// secular Newton loop: full unroll + 4-way split accumulators (breaks the
// 64-link dependent FADD chain that bound R13's k_wsec at 33.6us)
__global__ void k_wsec(float* __restrict__ out) {
    __shared__ float  smv[4][D_];
    __shared__ float  zsh[4][64];
    __shared__ float  redp[4][8];
    __shared__ float2 dw[4][NB];
    __shared__ float  vals[4][NB];
    __shared__ float  msqs[4];
    int bid = blockIdx.x, tid = threadIdx.x;
    int warp = tid >> 5, lane = tid & 31;
    int t0 = bid * 4;

    float mv[4];
#pragma unroll
    for (int q = 0; q < 4; q++) {
        mv[q] = g_M[(t0 + q) * D_ + tid];
        smv[q][tid] = mv[q];
    }
#pragma unroll
    for (int q = 0; q < 4; q++) {
        float p = mv[q] * mv[q];
#pragma unroll
        for (int o = 16; o > 0; o >>= 1)
            p += __shfl_down_sync(0xFFFFFFFFu, p, o);
        if (lane == 0) redp[q][warp] = p;
    }
    __syncthreads();

    // z_k = U_k . m  (warp-per-k; UT row loaded once, reused for 4 t's)
#pragma unroll
    for (int it = 0; it < 8; it++) {
        int k = warp * 8 + it;
        if (k < 63) {
            float a0 = 0.f, a1 = 0.f, a2 = 0.f, a3 = 0.f;
#pragma unroll
            for (int j = 0; j < 8; j++) {
                int d = lane + 32 * j;
                float u = g_UT[k * D_ + d];
                a0 += u * smv[0][d];
                a1 += u * smv[1][d];
                a2 += u * smv[2][d];
                a3 += u * smv[3][d];
            }
#pragma unroll
            for (int o = 16; o > 0; o >>= 1) {
                a0 += __shfl_down_sync(0xFFFFFFFFu, a0, o);
                a1 += __shfl_down_sync(0xFFFFFFFFu, a1, o);
                a2 += __shfl_down_sync(0xFFFFFFFFu, a2, o);
                a3 += __shfl_down_sync(0xFFFFFFFFu, a3, o);
            }
            if (lane == 0) {
                zsh[0][k] = a0; zsh[1][k] = a1;
                zsh[2][k] = a2; zsh[3][k] = a3;
            }
        }
    }
    __syncthreads();

    // weights: thread (sel*64 + i) fills dw[sel][i]
    {
        int sel = tid >> 6, i = tid & 63;
        if (i == 0) {
            float msq = 0.f;
#pragma unroll
            for (int w = 0; w < 8; w++) msq += redp[sel][w];
            float sz = 0.f;
            for (int k = 0; k < 63; k++) sz += zsh[sel][k] * zsh[sel][k];
            dw[sel][0] = make_float2(g_poles[0], fmaxf(msq - sz, 0.f));
            msqs[sel] = msq;
        } else {
            float z = zsh[sel][i - 1];
            dw[sel][i] = make_float2(g_poles[i], z * z);
        }
    }
    __syncthreads();

    int sel = tid >> 6, i = tid & 63;
    float S = 0.f;
#pragma unroll 8
    for (int k = 0; k < NB; k++) S += dw[sel][k].y;

    float lo = dw[sel][i].x;
    float hi = (i < 63) ? dw[sel][i + 1].x : dw[sel][63].x + S;
    float lam = 0.5f * (lo + hi);

    for (int it = 0; it < NIT; it++) {
        float f0 = 0.f, f1 = 0.f, f2 = 0.f, f3 = 0.f;
        float g0 = 0.f, g1 = 0.f, g2 = 0.f, g3 = 0.f;
#pragma unroll
        for (int k = 0; k < NB; k += 4) {
            float2 pa = dw[sel][k],     pb = dw[sel][k + 1];
            float2 pc = dw[sel][k + 2], pd = dw[sel][k + 3];
            float ra, rb, rc, rd;
            asm("rcp.approx.f32 %0, %1;" : "=f"(ra) : "f"(pa.x - lam));
            asm("rcp.approx.f32 %0, %1;" : "=f"(rb) : "f"(pb.x - lam));
            asm("rcp.approx.f32 %0, %1;" : "=f"(rc) : "f"(pc.x - lam));
            asm("rcp.approx.f32 %0, %1;" : "=f"(rd) : "f"(pd.x - lam));
            float ta = pa.y * ra, tb = pb.y * rb;
            float tc = pc.y * rc, td = pd.y * rd;
            f0 += ta; g0 += ta * ra;
            f1 += tb; g1 += tb * rb;
            f2 += tc; g2 += tc * rc;
            f3 += td; g3 += td * rd;
        }
        float f  = 1.f + ((f0 + f1) + (f2 + f3));
        float fp = (g0 + g1) + (g2 + g3);
        if (f > 0.f) hi = lam; else lo = lam;
        float ln = lam - __fdividef(f, fp);
        lam = (ln > lo && ln < hi) ? ln : 0.5f * (lo + hi);
    }

    float tr = msqs[sel] + g_trA;
    float v = fmaxf(__fdividef(lam, tr), EPSV);
    vals[sel][i] = v;
    __syncthreads();

    float ssum = 192.f * EPSV;
#pragma unroll 8
    for (int k = 0; k < NB; k++) ssum += vals[sel][k];
    float inv = __frcp_rn(ssum);

    float* o = out + (long)(t0 + sel) * D_;
    float ev = EPSV * inv;
    o[i]        = ev;               // positions   0..63  (zero eigs)
    o[i + 64]   = ev;               // positions  64..127
    o[i + 128]  = ev;               // positions 128..191
    o[i + 192]  = vals[sel][i] * inv;  // positions 192..255 (roots, ascending)
}

// ---------------- launcher ----------------
extern "C" void kernel_launch(void* const* d_in, const int* in_sizes, int n_in,
                              void* d_out, int out_size) {
    const int*   tokens = (const int*)d_in[0];
    const float* embed  = (const float*)d_in[1];
    const float* bubbles= (const float*)d_in[2];
    const float* mdecay = (const float*)d_in[3];
    float* out = (float*)d_out;

    cudaFuncSetAttribute(k_eigvec, cudaFuncAttributeMaxDynamicSharedMemorySize,
                         66560);

    k_scan_gram<<<96, 256>>>(tokens, embed, bubbles, mdecay);
    k_tridiag  <<<1, 64>>>();
    k_eigvec   <<<1, 1024, 66560>>>();
    k_buildU   <<<63, 256>>>();
    k_wsec     <<<256, 256>>>(out);
    (void)in_sizes; (void)n_in; (void)out_size;
}

// round 15
// speedup vs baseline: 1.0539x; 1.0380x over previous
#include <cuda_runtime.h>
#include <cuda_bf16.h>
#include <math.h>

#define D_    256
#define NB    64
#define SEQ   1024
#define EPSV  1e-10f
#define NIT   12
#define NROUNDS 6          // multisection rounds, 9x contraction each

// closed-form constants
#define ALPHA     0.32768f        // (1-2*ETA)^5
#define ALPHA2_64 0.0016777216f   // ALPHA^2 / 64
#define ALPHA_8   0.04096f        // ALPHA / 8
#define BETA      0.59049f        // (1-ETA)^5
#define OMBETA    0.40951f        // 1 - BETA

// ---------------- device scratch (no allocations allowed) ----------------
__device__ float g_D0[NB * D_];         // deviations
__device__ float g_Gg[NB * NB];         // Gram matrix
__device__ float g_V[62 * NB];          // Householder reflectors
__device__ float g_tau[64];             // reflector taus
__device__ float g_diag[NB];            // tridiag diagonal
__device__ float g_off[NB];             // tridiag off-diagonal
__device__ float g_Wg[NB * NB];         // eigenvectors of G (rows i, cols k asc)
__device__ float g_poles[NB];           // poles[0]=0, poles[1..63] ascending
__device__ float g_trA;                 // sum of kept poles
__device__ float g_M[SEQ * D_];         // m_t per step

// ------ 1) fused scan (32 blocks) + gram (64 blocks)  <<<96,256>>> -------
__global__ void k_scan_gram(const int* __restrict__ tokens,
                            const float* __restrict__ embed,
                            const float* __restrict__ bubbles,
                            const float* __restrict__ mdecay) {
    __shared__ float rowi[D_];
    __shared__ float bmsh[D_];
    __shared__ int   tk[128];
    int t = threadIdx.x;

    if (blockIdx.x < 64) {
        // ---- gram block i: G[i][*] = (a^2/64) D0_i . D0_j ----
        int i = blockIdx.x;
        float s = 0.f;
#pragma unroll 8
        for (int r = 0; r < NB; r++) s += bubbles[r * D_ + t];
        float bm = s * (1.f / NB);
        float v = bubbles[i * D_ + t] - bm;
        rowi[t] = v;
        bmsh[t] = bm;
        g_D0[i * D_ + t] = v;
        __syncthreads();

        int lane = t & 31, w = t >> 5;
#pragma unroll
        for (int it = 0; it < 8; it++) {
            int j = w * 8 + it;
            const float* bj = bubbles + j * D_;
            float acc = 0.f;
#pragma unroll
            for (int m = 0; m < 8; m++) {
                int d = lane + 32 * m;
                acc += rowi[d] * (bj[d] - bmsh[d]);
            }
#pragma unroll
            for (int o = 16; o > 0; o >>= 1)
                acc += __shfl_down_sync(0xFFFFFFFFu, acc, o);
            if (lane == 0) g_Gg[i * NB + j] = acc * ALPHA2_64;
        }
    } else {
        // ---- scan block: contraction a ~ 0.778, a^96 ~ 3e-11 warmup ----
        int c = blockIdx.x - 64, d = t;
        float s0 = 0.f, s1 = 0.f;
#pragma unroll 8
        for (int r = 0; r < NB; r += 2) {
            s0 += bubbles[r * D_ + d];
            s1 += bubbles[(r + 1) * D_ + d];
        }
        float cb = BETA * (s0 + s1) * (1.f / NB);
        float decay = 1.f / (1.f + expf(-mdecay[0]));
        float omdecay = 1.f - decay;

        int tout = c * 32;
        int tstart = tout - 96; if (tstart < 0) tstart = 0;
        int tend = tout + 32;
        int nwin = tend - tstart;
        if (d < nwin) tk[d] = tokens[tstart + d];
        __syncthreads();

        float mm = 0.f;
        float xs[8];
#pragma unroll
        for (int j = 0; j < 8; j++) xs[j] = embed[(long)tk[j] * D_ + d];
        for (int t0 = tstart; t0 < tend; t0 += 8) {
#pragma unroll
            for (int j = 0; j < 8; j++) {
                int tt = t0 + j;
                float x = xs[j];
                int tn = t0 + 8 + j;
                if (tn < tend) xs[j] = embed[(long)tk[tn - tstart] * D_ + d];
                float m = cb + OMBETA * (x + decay * mm);
                if (tt >= tout) g_M[tt * D_ + d] = m;
                mm = decay * mm + omdecay * m;
            }
        }
    }
}

// ------ 2) register-resident Householder tridiagonalization <<<1,64>>> ---
__global__ void __launch_bounds__(64) k_tridiag() {
    __shared__ float vsh[NB], wsh[NB], red2[2];
    __shared__ float x0sh;
    float row[NB];
    int r = threadIdx.x, lane = r & 31, warp = r >> 5;

#pragma unroll
    for (int c = 0; c < NB; c++) row[c] = g_Gg[r * NB + c];
    float x = row[0];

#pragma unroll 1
    for (int k = 0; k < 62; k++) {
        int n0 = k + 1;
        float xm = (r >= n0) ? x : 0.f;
        float s = xm * xm;
#pragma unroll
        for (int o = 16; o > 0; o >>= 1) s += __shfl_xor_sync(0xFFFFFFFFu, s, o);
        if (lane == 0) red2[warp] = s;
        if (r == n0) x0sh = xm;
        __syncthreads();
        float sum = red2[0] + red2[1];
        float x0 = x0sh;
        float sigma = sqrtf(sum);
        float sgn = (x0 >= 0.f) ? 1.f : -1.f;
        float tau = (sum > 1e-30f)
                  ? __fdividef(1.f, sigma * (sigma + fabsf(x0))) : 0.f;
        if (r == 0) { g_off[k] = -sgn * sigma; g_tau[k] = tau; }
        float v = (r == n0) ? x0 + sgn * sigma : xm;   // xm==0 for r<n0
        vsh[r] = v;
        g_V[k * NB + r] = v;
        __syncthreads();
        float a0 = 0.f, a1 = 0.f, a2 = 0.f, a3 = 0.f;
#pragma unroll
        for (int c = 0; c < NB; c += 4) {
            a0 += row[c]     * vsh[c];
            a1 += row[c + 1] * vsh[c + 1];
            a2 += row[c + 2] * vsh[c + 2];
            a3 += row[c + 3] * vsh[c + 3];
        }
        float p = tau * ((a0 + a1) + (a2 + a3));
        float pv = p * v;
#pragma unroll
        for (int o = 16; o > 0; o >>= 1) pv += __shfl_xor_sync(0xFFFFFFFFu, pv, o);
        if (lane == 0) red2[warp] = pv;
        __syncthreads();
        float K = 0.5f * tau * (red2[0] + red2[1]);
        float w = (r >= n0) ? (p - K * v) : 0.f;
        wsh[r] = w;
        __syncthreads();
        float xn = x;
#pragma unroll
        for (int c = 0; c < NB; c++) {
            float nv = row[c] - v * wsh[c] - w * vsh[c];
            row[c] = nv;
            if (c == n0) xn = nv;
        }
        x = xn;
    }

    float dg = 0.f;
#pragma unroll
    for (int c = 0; c < NB; c++) if (c == r) dg = row[c];
    g_diag[r] = dg;
    if (r == 63) g_off[62] = row[62];
    if (r == 0)  g_off[63] = 0.f;
}

// ------ 3) eigvecs: multisection Sturm + invit + backtransform -----------
__global__ void k_eigvec() {          // <<<1, 1024, 66560>>>
    extern __shared__ float sm[];
    float* E  = sm;                   // 64x65 eigvec columns
    float* DD = sm + 4160;            // invit scratch: reciprocal pivots
    float* YY = sm + 8320;            // invit scratch
    float* V  = sm + 12480;           // reflectors [k][r], pitch 65

    __shared__ float diag[64], off[64], b2[64], eig[64], tauv[64];
    __shared__ float red[32];
    __shared__ int   oflag[64];
    __shared__ float sc_lo, sc_hi;

    int tid = threadIdx.x, lane = tid & 31, warp = tid >> 5;

    if (tid < 64) { diag[tid] = g_diag[tid]; off[tid] = g_off[tid]; }
    if (tid < 62) tauv[tid] = g_tau[tid];
    for (int e = tid; e < 62 * NB; e += 1024)
        V[(e >> 6) * 65 + (e & 63)] = g_V[e];
    __syncthreads();
    if (tid < 63) b2[tid] = off[tid] * off[tid];
    if (tid == 0) {
        float lo = 1e30f, hi = -1e30f;
        for (int i = 0; i < 64; i++) {
            float om = (i > 0) ? fabsf(off[i - 1]) : 0.f;
            float op = (i < 63) ? fabsf(off[i]) : 0.f;
            lo = fminf(lo, diag[i] - om - op);
            hi = fmaxf(hi, diag[i] + om + op);
        }
        float mg = 1e-6f * fmaxf(fabsf(lo), fabsf(hi)) + 1e-30f;
        sc_lo = lo - mg; sc_hi = hi + mg;
    }
    __syncthreads();

    // ---- multisection Sturm: 8 threads per eigenvalue ----
    if (tid < 512) {
        int i = tid >> 3, s8 = tid & 7;
        float lo = sc_lo, hi = sc_hi;
        for (int round = 0; round < NROUNDS; round++) {
            float step = (hi - lo) * (1.f / 9.f);
            float mid = lo + step * (float)(s8 + 1);
            float d = diag[0] - mid;
            int cnt = (d < 0.f);
            for (int j = 1; j < 64; j++) {
                float dg = (fabsf(d) < 1e-25f) ? -1e-25f : d;
                d = (diag[j] - mid) - __fdividef(b2[j - 1], dg);
                cnt += (d < 0.f);
            }
            unsigned bal = __ballot_sync(0xFFFFFFFFu, cnt <= i);
            unsigned bits = (bal >> (lane & 24)) & 0xFFu;
            int p = __popc(bits);
            lo = lo + step * (float)p;
            hi = lo + step;
        }
        if (s8 == 0) eig[i] = 0.5f * (lo + hi);
    }
    __syncthreads();

    // ---- inverse iteration (reciprocal pivots cached in DD) ----
    if (tid < 64) {
        int i = tid;
        float scale = fmaxf(fabsf(sc_hi), fabsf(sc_lo));
        float lam = eig[i] + scale * 2e-6f;
        unsigned h = (unsigned)(i * 2654435761u) ^ 0x9E3779B9u;
        for (int j = 0; j < 64; j++) {
            h = h * 1664525u + 1013904223u;
            E[j * 65 + i] = 1.f + (float)(h >> 16) * 1.52587890625e-05f;
        }
        for (int iter = 0; iter < 3; iter++) {
            float d0 = diag[0] - lam;
            d0 = (fabsf(d0) < 1e-20f) ? copysignf(1e-20f, d0) : d0;
            float rc;
            asm("rcp.approx.f32 %0, %1;" : "=f"(rc) : "f"(d0));
            DD[i * 65 + 0] = rc;
            float yprev = E[0 * 65 + i];
            YY[i * 65 + 0] = yprev;
            for (int j = 1; j < 64; j++) {
                float m = off[j - 1] * rc;
                float dcur = (diag[j] - lam) - m * off[j - 1];
                dcur = (fabsf(dcur) < 1e-20f) ? copysignf(1e-20f, dcur) : dcur;
                float rcn;
                asm("rcp.approx.f32 %0, %1;" : "=f"(rcn) : "f"(dcur));
                float ycur = E[j * 65 + i] - m * yprev;
                DD[i * 65 + j] = rcn;
                YY[i * 65 + j] = ycur;
                rc = rcn; yprev = ycur;
            }
            float vj = yprev * rc;
            E[63 * 65 + i] = vj;
            float nrm = vj * vj;
            for (int j = 62; j >= 0; j--) {
                vj = (YY[i * 65 + j] - off[j] * vj) * DD[i * 65 + j];
                E[j * 65 + i] = vj;
                nrm += vj * vj;
            }
            float inv = rsqrtf(nrm);
            for (int j = 0; j < 64; j++) E[j * 65 + i] *= inv;
        }
    }
    __syncthreads();

    // ---- gap-flagged neighbor re-orthogonalization ----
    if (tid < 64) {
        float scale = fmaxf(fabsf(eig[63]), fabsf(eig[0]));
        oflag[tid] = (tid > 0) && (eig[tid] - eig[tid - 1] < 1e-3f * scale);
    }
    __syncthreads();
    for (int i = 1; i < 64; i++) {
        if (!oflag[i]) continue;
        float pr = (tid < 64) ? E[tid * 65 + i] * E[tid * 65 + i - 1] : 0.f;
#pragma unroll
        for (int o = 16; o > 0; o >>= 1)
            pr += __shfl_down_sync(0xFFFFFFFFu, pr, o);
        if (lane == 0 && tid < 64) red[warp] = pr;
        __syncthreads();
        float dot = red[0] + red[1];
        float nv = 0.f;
        if (tid < 64) {
            E[tid * 65 + i] -= dot * E[tid * 65 + i - 1];
            nv = E[tid * 65 + i] * E[tid * 65 + i];
        }
#pragma unroll
        for (int o = 16; o > 0; o >>= 1)
            nv += __shfl_down_sync(0xFFFFFFFFu, nv, o);
        if (lane == 0 && tid < 64) red[warp] = nv;
        __syncthreads();
        float sc = rsqrtf(red[0] + red[1] + 1e-30f);
        if (tid < 64) E[tid * 65 + i] *= sc;
        __syncthreads();
    }

    // ---- back-transform: apply reflectors k = 61..0 (cols independent) --
    {
        int col = tid >> 4, sub = tid & 15;
        for (int k = 61; k >= 0; k--) {
            int n0 = k + 1, n2 = 63 - k;
            float tau = tauv[k];
            float acc = 0.f;
            for (int r = sub; r < n2; r += 16)
                acc += V[k * 65 + n0 + r] * E[(n0 + r) * 65 + col];
#pragma unroll
            for (int o = 8; o > 0; o >>= 1)
                acc += __shfl_xor_sync(0xFFFFFFFFu, acc, o, 16);
            float w = tau * acc;
            for (int r = sub; r < n2; r += 16)
                E[(n0 + r) * 65 + col] -= w * V[k * 65 + n0 + r];
        }
    }
    __syncthreads();

    if (tid == 0) {
        g_poles[0] = 0.f;
        float s = 0.f;
        for (int k = 1; k < 64; k++) {
            float p = fmaxf(eig[k], 1e-12f);
            g_poles[k] = p;
            s += p;
        }
        g_trA = s;
    }
    for (int e = tid; e < NB * NB; e += 1024)
        g_Wg[e] = E[(e >> 6) * 65 + (e & 63)];
}

// ------ 4) fused weights + secular, 4 timesteps/block <<<256,256>>> ------
// z computed directly from Wg and D0 (buildU eliminated):
//   y = D0 . m  (64 dots), z_k = scale_k * (W^T y)_k, scale = a/8/sqrt(lam)
__global__ void k_wsec(float* __restrict__ out) {
    __shared__ float  smv[4][D_];
    __shared__ float  ysh[4][NB];
    __shared__ float  wsm[NB * NB];     // Wg row-major [i][k]
    __shared__ float  scs[64];          // scale for z index k (pole k+1)
    __shared__ float  zsh[4][64];
    __shared__ float  redp[4][8];
    __shared__ float2 dw[4][NB];
    __shared__ float  vals[4][NB];
    __shared__ float  msqs[4];
    int bid = blockIdx.x, tid = threadIdx.x;
    int warp = tid >> 5, lane = tid & 31;
    int t0 = bid * 4;

    // load W (L2-hot, 16KB) and scales
#pragma unroll
    for (int e = 0; e < 16; e++) wsm[tid + 256 * e] = g_Wg[tid + 256 * e];
    if (tid < 63) scs[tid] = ALPHA_8 * rsqrtf(fmaxf(g_poles[tid + 1], 1e-20f));

    float mv[4];
#pragma unroll
    for (int q = 0; q < 4; q++) {
        mv[q] = g_M[(t0 + q) * D_ + tid];
        smv[q][tid] = mv[q];
    }
#pragma unroll
    for (int q = 0; q < 4; q++) {
        float p = mv[q] * mv[q];
#pragma unroll
        for (int o = 16; o > 0; o >>= 1)
            p += __shfl_down_sync(0xFFFFFFFFu, p, o);
        if (lane == 0) redp[q][warp] = p;
    }
    __syncthreads();

    // y_i = D0_i . m  (warp-per-row; D0 row loaded once, reused for 4 t's)
#pragma unroll
    for (int it = 0; it < 8; it++) {
        int i = warp * 8 + it;
        float a0 = 0.f, a1 = 0.f, a2 = 0.f, a3 = 0.f;
#pragma unroll
        for (int j = 0; j < 8; j++) {
            int d = lane + 32 * j;
            float u = __ldg(&g_D0[i * D_ + d]);
            a0 += u * smv[0][d];
            a1 += u * smv[1][d];
            a2 += u * smv[2][d];
            a3 += u * smv[3][d];
        }
#pragma unroll
        for (int o = 16; o > 0; o >>= 1) {
            a0 += __shfl_down_sync(0xFFFFFFFFu, a0, o);
            a1 += __shfl_down_sync(0xFFFFFFFFu, a1, o);
            a2 += __shfl_down_sync(0xFFFFFFFFu, a2, o);
            a3 += __shfl_down_sync(0xFFFFFFFFu, a3, o);
        }
        if (lane == 0) {
            ysh[0][i] = a0; ysh[1][i] = a1;
            ysh[2][i] = a2; ysh[3][i] = a3;
        }
    }
    __syncthreads();

    // z_k = scale_k * sum_i W[i][k+1] * y_i   (thread (sel,k), k<63)
    {
        int sel = tid >> 6, k = tid & 63;
        if (k < 63) {
            float a0 = 0.f, a1 = 0.f;
#pragma unroll
            for (int i = 0; i < NB; i += 2) {
                a0 += wsm[i * 64 + k + 1]       * ysh[sel][i];
                a1 += wsm[(i + 1) * 64 + k + 1] * ysh[sel][i + 1];
            }
            zsh[sel][k] = scs[k] * (a0 + a1);
        }
    }
    __syncthreads();

    // weights: thread (sel*64 + i) fills dw[sel][i]
    {
        int sel = tid >> 6, i = tid & 63;
        if (i == 0) {
            float msq = 0.f;
#pragma unroll
            for (int w = 0; w < 8; w++) msq += redp[sel][w];
            float sz = 0.f;
            for (int k = 0; k < 63; k++) sz += zsh[sel][k] * zsh[sel][k];
            dw[sel][0] = make_float2(g_poles[0], fmaxf(msq - sz, 0.f));
            msqs[sel] = msq;
        } else {
            float z = zsh[sel][i - 1];
            dw[sel][i] = make_float2(g_poles[i], z * z);
        }
    }
    __syncthreads();

    int sel = tid >> 6, i = tid & 63;
    float S = 0.f;
#pragma unroll 8
    for (int k = 0; k < NB; k++) S += dw[sel][k].y;

    float lo = dw[sel][i].x;
    float hi = (i < 63) ? dw[sel][i + 1].x : dw[sel][63].x + S;
    float lam = 0.5f * (lo + hi);

    for (int it = 0; it < NIT; it++) {
        float f = 1.f, fp = 0.f;
#pragma unroll 8
        for (int k = 0; k < NB; k++) {
            float2 p = dw[sel][k];
            float diff = p.x - lam;
            float rc;
            asm("rcp.approx.f32 %0, %1;" : "=f"(rc) : "f"(diff));
            float term = p.y * rc;
            f  += term;
            fp += term * rc;
        }
        if (f > 0.f) hi = lam; else lo = lam;
        float ln = lam - __fdividef(f, fp);
        lam = (ln > lo && ln < hi) ? ln : 0.5f * (lo + hi);
    }

    float tr = msqs[sel] + g_trA;
    float v = fmaxf(__fdividef(lam, tr), EPSV);
    vals[sel][i] = v;
    __syncthreads();

    float ssum = 192.f * EPSV;
#pragma unroll 8
    for (int k = 0; k < NB; k++) ssum += vals[sel][k];
    float inv = __frcp_rn(ssum);

    float* o = out + (long)(t0 + sel) * D_;
    float ev = EPSV * inv;
    o[i]        = ev;               // positions   0..63  (zero eigs)
    o[i + 64]   = ev;               // positions  64..127
    o[i + 128]  = ev;               // positions 128..191
    o[i + 192]  = vals[sel][i] * inv;  // positions 192..255 (roots, ascending)
}

// ---------------- launcher ----------------
extern "C" void kernel_launch(void* const* d_in, const int* in_sizes, int n_in,
                              void* d_out, int out_size) {
    const int*   tokens = (const int*)d_in[0];
    const float* embed  = (const float*)d_in[1];
    const float* bubbles= (const float*)d_in[2];
    const float* mdecay = (const float*)d_in[3];
    float* out = (float*)d_out;

    cudaFuncSetAttribute(k_eigvec, cudaFuncAttributeMaxDynamicSharedMemorySize,
                         66560);

    k_scan_gram<<<96, 256>>>(tokens, embed, bubbles, mdecay);
    k_tridiag  <<<1, 64>>>();
    k_eigvec   <<<1, 1024, 66560>>>();
    k_wsec     <<<256, 256>>>(out);
    (void)in_sizes; (void)n_in; (void)out_size;
}

// round 16
// speedup vs baseline: 1.0785x; 1.0234x over previous
#include <cuda_runtime.h>
#include <cuda_bf16.h>
#include <math.h>

#define D_    256
#define NB    64
#define SEQ   1024
#define EPSV  1e-10f
#define NIT   12
#define NROUNDS 6          // multisection rounds, 9x contraction each

// closed-form constants
#define ALPHA     0.32768f        // (1-2*ETA)^5
#define ALPHA2_64 0.0016777216f   // ALPHA^2 / 64
#define ALPHA_8   0.04096f        // ALPHA / 8
#define BETA      0.59049f        // (1-ETA)^5
#define OMBETA    0.40951f        // 1 - BETA

// ---------------- device scratch (no allocations allowed) ----------------
__device__ float g_D0[NB * D_];         // deviations
__device__ float g_Gg[NB * NB];         // Gram matrix
__device__ float g_V[62 * NB];          // Householder reflectors
__device__ float g_tau[64];             // reflector taus
__device__ float g_diag[NB];            // tridiag diagonal
__device__ float g_off[NB];             // tridiag off-diagonal
__device__ float g_Wg[NB * NB];         // eigenvectors of G (rows i, cols k asc)
__device__ float g_poles[NB];           // poles[0]=0, poles[1..63] ascending
__device__ float g_trA;                 // sum of kept poles
__device__ float g_M[SEQ * D_];         // m_t per step

// ------ 1) fused scan (32 blocks) + gram (64 blocks)  <<<96,256>>> -------
__global__ void k_scan_gram(const int* __restrict__ tokens,
                            const float* __restrict__ embed,
                            const float* __restrict__ bubbles,
                            const float* __restrict__ mdecay) {
    __shared__ float rowi[D_];
    __shared__ float bmsh[D_];
    __shared__ int   tk[128];
    int t = threadIdx.x;

    if (blockIdx.x < 64) {
        // ---- gram block i: G[i][*] = (a^2/64) D0_i . D0_j ----
        int i = blockIdx.x;
        float s = 0.f;
#pragma unroll 8
        for (int r = 0; r < NB; r++) s += bubbles[r * D_ + t];
        float bm = s * (1.f / NB);
        float v = bubbles[i * D_ + t] - bm;
        rowi[t] = v;
        bmsh[t] = bm;
        g_D0[i * D_ + t] = v;
        __syncthreads();

        int lane = t & 31, w = t >> 5;
#pragma unroll
        for (int it = 0; it < 8; it++) {
            int j = w * 8 + it;
            const float* bj = bubbles + j * D_;
            float acc = 0.f;
#pragma unroll
            for (int m = 0; m < 8; m++) {
                int d = lane + 32 * m;
                acc += rowi[d] * (bj[d] - bmsh[d]);
            }
#pragma unroll
            for (int o = 16; o > 0; o >>= 1)
                acc += __shfl_down_sync(0xFFFFFFFFu, acc, o);
            if (lane == 0) g_Gg[i * NB + j] = acc * ALPHA2_64;
        }
    } else {
        // ---- scan block: contraction a ~ 0.778, a^96 ~ 3e-11 warmup ----
        int c = blockIdx.x - 64, d = t;
        float s0 = 0.f, s1 = 0.f;
#pragma unroll 8
        for (int r = 0; r < NB; r += 2) {
            s0 += bubbles[r * D_ + d];
            s1 += bubbles[(r + 1) * D_ + d];
        }
        float cb = BETA * (s0 + s1) * (1.f / NB);
        float decay = 1.f / (1.f + expf(-mdecay[0]));
        float omdecay = 1.f - decay;

        int tout = c * 32;
        int tstart = tout - 96; if (tstart < 0) tstart = 0;
        int tend = tout + 32;
        int nwin = tend - tstart;
        if (d < nwin) tk[d] = tokens[tstart + d];
        __syncthreads();

        float mm = 0.f;
        float xs[8];
#pragma unroll
        for (int j = 0; j < 8; j++) xs[j] = embed[(long)tk[j] * D_ + d];
        for (int t0 = tstart; t0 < tend; t0 += 8) {
#pragma unroll
            for (int j = 0; j < 8; j++) {
                int tt = t0 + j;
                float x = xs[j];
                int tn = t0 + 8 + j;
                if (tn < tend) xs[j] = embed[(long)tk[tn - tstart] * D_ + d];
                float m = cb + OMBETA * (x + decay * mm);
                if (tt >= tout) g_M[tt * D_ + d] = m;
                mm = decay * mm + omdecay * m;
            }
        }
    }
}

// ------ 2) register-resident Householder tridiagonalization <<<1,64>>> ---
// all smem broadcast traffic via LDS.128 (vsh/wsh float4-aliased)
__global__ void __launch_bounds__(64) k_tridiag() {
    __shared__ float4 vsh4[16], wsh4[16];
    __shared__ float red2[2];
    __shared__ float x0sh;
    float* vsh = (float*)vsh4;
    float* wsh = (float*)wsh4;
    float row[NB];
    int r = threadIdx.x, lane = r & 31, warp = r >> 5;

    {
        const float4* g4 = (const float4*)(g_Gg + r * NB);
#pragma unroll
        for (int c4 = 0; c4 < 16; c4++) {
            float4 g = g4[c4];
            row[c4 * 4]     = g.x;
            row[c4 * 4 + 1] = g.y;
            row[c4 * 4 + 2] = g.z;
            row[c4 * 4 + 3] = g.w;
        }
    }
    float x = row[0];

#pragma unroll 1
    for (int k = 0; k < 62; k++) {
        int n0 = k + 1;
        float xm = (r >= n0) ? x : 0.f;
        float s = xm * xm;
#pragma unroll
        for (int o = 16; o > 0; o >>= 1) s += __shfl_xor_sync(0xFFFFFFFFu, s, o);
        if (lane == 0) red2[warp] = s;
        if (r == n0) x0sh = xm;
        __syncthreads();
        float sum = red2[0] + red2[1];
        float x0 = x0sh;
        float sigma = sqrtf(sum);
        float sgn = (x0 >= 0.f) ? 1.f : -1.f;
        float tau = (sum > 1e-30f)
                  ? __fdividef(1.f, sigma * (sigma + fabsf(x0))) : 0.f;
        if (r == 0) { g_off[k] = -sgn * sigma; g_tau[k] = tau; }
        float v = (r == n0) ? x0 + sgn * sigma : xm;   // xm==0 for r<n0
        vsh[r] = v;
        g_V[k * NB + r] = v;
        __syncthreads();
        // dot: row . v with LDS.128 broadcasts
        float a0 = 0.f, a1 = 0.f, a2 = 0.f, a3 = 0.f;
#pragma unroll
        for (int c4 = 0; c4 < 16; c4++) {
            float4 vv = vsh4[c4];
            a0 += row[c4 * 4]     * vv.x;
            a1 += row[c4 * 4 + 1] * vv.y;
            a2 += row[c4 * 4 + 2] * vv.z;
            a3 += row[c4 * 4 + 3] * vv.w;
        }
        float p = tau * ((a0 + a1) + (a2 + a3));
        float pv = p * v;
#pragma unroll
        for (int o = 16; o > 0; o >>= 1) pv += __shfl_xor_sync(0xFFFFFFFFu, pv, o);
        if (lane == 0) red2[warp] = pv;
        __syncthreads();
        float K = 0.5f * tau * (red2[0] + red2[1]);
        float w = (r >= n0) ? (p - K * v) : 0.f;
        wsh[r] = w;
        __syncthreads();
        // rank-2 update with LDS.128 broadcasts; predicated capture of row[n0]
        float xn = x;
#pragma unroll
        for (int c4 = 0; c4 < 16; c4++) {
            float4 vv = vsh4[c4];
            float4 ww = wsh4[c4];
            float nv0 = row[c4 * 4]     - v * ww.x - w * vv.x;
            float nv1 = row[c4 * 4 + 1] - v * ww.y - w * vv.y;
            float nv2 = row[c4 * 4 + 2] - v * ww.z - w * vv.z;
            float nv3 = row[c4 * 4 + 3] - v * ww.w - w * vv.w;
            row[c4 * 4]     = nv0;
            row[c4 * 4 + 1] = nv1;
            row[c4 * 4 + 2] = nv2;
            row[c4 * 4 + 3] = nv3;
            if (c4 * 4     == n0) xn = nv0;
            if (c4 * 4 + 1 == n0) xn = nv1;
            if (c4 * 4 + 2 == n0) xn = nv2;
            if (c4 * 4 + 3 == n0) xn = nv3;
        }
        x = xn;
    }

    float dg = 0.f;
#pragma unroll
    for (int c = 0; c < NB; c++) if (c == r) dg = row[c];
    g_diag[r] = dg;
    if (r == 63) g_off[62] = row[62];
    if (r == 0)  g_off[63] = 0.f;
}

// ------ 3) eigvecs: multisection Sturm + invit + backtransform -----------
__global__ void k_eigvec() {          // <<<1, 1024, 66560>>>
    extern __shared__ float sm[];
    float* E  = sm;                   // 64x65 eigvec columns
    float* DD = sm + 4160;            // invit scratch: reciprocal pivots
    float* YY = sm + 8320;            // invit scratch
    float* V  = sm + 12480;           // reflectors [k][r], pitch 65

    __shared__ float diag[64], off[64], b2[64], eig[64], tauv[64];
    __shared__ float red[32];
    __shared__ int   oflag[64];
    __shared__ float sc_lo, sc_hi;

    int tid = threadIdx.x, lane = tid & 31, warp = tid >> 5;

    if (tid < 64) { diag[tid] = g_diag[tid]; off[tid] = g_off[tid]; }
    if (tid < 62) tauv[tid] = g_tau[tid];
    for (int e = tid; e < 62 * NB; e += 1024)
        V[(e >> 6) * 65 + (e & 63)] = g_V[e];
    __syncthreads();
    if (tid < 63) b2[tid] = off[tid] * off[tid];
    if (tid == 0) {
        float lo = 1e30f, hi = -1e30f;
        for (int i = 0; i < 64; i++) {
            float om = (i > 0) ? fabsf(off[i - 1]) : 0.f;
            float op = (i < 63) ? fabsf(off[i]) : 0.f;
            lo = fminf(lo, diag[i] - om - op);
            hi = fmaxf(hi, diag[i] + om + op);
        }
        float mg = 1e-6f * fmaxf(fabsf(lo), fabsf(hi)) + 1e-30f;
        sc_lo = lo - mg; sc_hi = hi + mg;
    }
    __syncthreads();

    // ---- multisection Sturm: 8 threads per eigenvalue ----
    if (tid < 512) {
        int i = tid >> 3, s8 = tid & 7;
        float lo = sc_lo, hi = sc_hi;
        for (int round = 0; round < NROUNDS; round++) {
            float step = (hi - lo) * (1.f / 9.f);
            float mid = lo + step * (float)(s8 + 1);
            float d = diag[0] - mid;
            int cnt = (d < 0.f);
            for (int j = 1; j < 64; j++) {
                float dg = (fabsf(d) < 1e-25f) ? -1e-25f : d;
                d = (diag[j] - mid) - __fdividef(b2[j - 1], dg);
                cnt += (d < 0.f);
            }
            unsigned bal = __ballot_sync(0xFFFFFFFFu, cnt <= i);
            unsigned bits = (bal >> (lane & 24)) & 0xFFu;
            int p = __popc(bits);
            lo = lo + step * (float)p;
            hi = lo + step;
        }
        if (s8 == 0) eig[i] = 0.5f * (lo + hi);
    }
    __syncthreads();

    // ---- inverse iteration (reciprocal pivots cached in DD) ----
    if (tid < 64) {
        int i = tid;
        float scale = fmaxf(fabsf(sc_hi), fabsf(sc_lo));
        float lam = eig[i] + scale * 2e-6f;
        unsigned h = (unsigned)(i * 2654435761u) ^ 0x9E3779B9u;
        for (int j = 0; j < 64; j++) {
            h = h * 1664525u + 1013904223u;
            E[j * 65 + i] = 1.f + (float)(h >> 16) * 1.52587890625e-05f;
        }
        for (int iter = 0; iter < 3; iter++) {
            float d0 = diag[0] - lam;
            d0 = (fabsf(d0) < 1e-20f) ? copysignf(1e-20f, d0) : d0;
            float rc;
            asm("rcp.approx.f32 %0, %1;" : "=f"(rc) : "f"(d0));
            DD[i * 65 + 0] = rc;
            float yprev = E[0 * 65 + i];
            YY[i * 65 + 0] = yprev;
            for (int j = 1; j < 64; j++) {
                float m = off[j - 1] * rc;
                float dcur = (diag[j] - lam) - m * off[j - 1];
                dcur = (fabsf(dcur) < 1e-20f) ? copysignf(1e-20f, dcur) : dcur;
                float rcn;
                asm("rcp.approx.f32 %0, %1;" : "=f"(rcn) : "f"(dcur));
                float ycur = E[j * 65 + i] - m * yprev;
                DD[i * 65 + j] = rcn;
                YY[i * 65 + j] = ycur;
                rc = rcn; yprev = ycur;
            }
            float vj = yprev * rc;
            E[63 * 65 + i] = vj;
            float nrm = vj * vj;
            for (int j = 62; j >= 0; j--) {
                vj = (YY[i * 65 + j] - off[j] * vj) * DD[i * 65 + j];
                E[j * 65 + i] = vj;
                nrm += vj * vj;
            }
            float inv = rsqrtf(nrm);
            for (int j = 0; j < 64; j++) E[j * 65 + i] *= inv;
        }
    }
    __syncthreads();

    // ---- gap-flagged neighbor re-orthogonalization ----
    if (tid < 64) {
        float scale = fmaxf(fabsf(eig[63]), fabsf(eig[0]));
        oflag[tid] = (tid > 0) && (eig[tid] - eig[tid - 1] < 1e-3f * scale);
    }
    __syncthreads();
    for (int i = 1; i < 64; i++) {
        if (!oflag[i]) continue;
        float pr = (tid < 64) ? E[tid * 65 + i] * E[tid * 65 + i - 1] : 0.f;
#pragma unroll
        for (int o = 16; o > 0; o >>= 1)
            pr += __shfl_down_sync(0xFFFFFFFFu, pr, o);
        if (lane == 0 && tid < 64) red[warp] = pr;
        __syncthreads();
        float dot = red[0] + red[1];
        float nv = 0.f;
        if (tid < 64) {
            E[tid * 65 + i] -= dot * E[tid * 65 + i - 1];
            nv = E[tid * 65 + i] * E[tid * 65 + i];
        }
#pragma unroll
        for (int o = 16; o > 0; o >>= 1)
            nv += __shfl_down_sync(0xFFFFFFFFu, nv, o);
        if (lane == 0 && tid < 64) red[warp] = nv;
        __syncthreads();
        float sc = rsqrtf(red[0] + red[1] + 1e-30f);
        if (tid < 64) E[tid * 65 + i] *= sc;
        __syncthreads();
    }

    // ---- back-transform: apply reflectors k = 61..0 (cols independent) --
    {
        int col = tid >> 4, sub = tid & 15;
        for (int k = 61; k >= 0; k--) {
            int n0 = k + 1, n2 = 63 - k;
            float tau = tauv[k];
            float acc = 0.f;
            for (int r = sub; r < n2; r += 16)
                acc += V[k * 65 + n0 + r] * E[(n0 + r) * 65 + col];
#pragma unroll
            for (int o = 8; o > 0; o >>= 1)
                acc += __shfl_xor_sync(0xFFFFFFFFu, acc, o, 16);
            float w = tau * acc;
            for (int r = sub; r < n2; r += 16)
                E[(n0 + r) * 65 + col] -= w * V[k * 65 + n0 + r];
        }
    }
    __syncthreads();

    if (tid == 0) {
        g_poles[0] = 0.f;
        float s = 0.f;
        for (int k = 1; k < 64; k++) {
            float p = fmaxf(eig[k], 1e-12f);
            g_poles[k] = p;
            s += p;
        }
        g_trA = s;
    }
    for (int e = tid; e < NB * NB; e += 1024)
        g_Wg[e] = E[(e >> 6) * 65 + (e & 63)];
}

// ------ 4) fused weights + secular, 4 timesteps/block <<<256,256>>> ------
// z computed directly from Wg and D0; (pole,w2) pairs packed into float4
// so the secular loop does 32 LDS.128 per Newton iter; S = msq identically.
__global__ void k_wsec(float* __restrict__ out) {
    __shared__ float  smv[4][D_];
    __shared__ float  ysh[4][NB];
    __shared__ float  wsm[NB * NB];     // Wg row-major [i][k]
    __shared__ float  scs[64];          // scale for z index k (pole k+1)
    __shared__ float  zsh[4][64];
    __shared__ float  redp[4][8];
    __shared__ float4 dw4[4][32];       // [sel][k4] = (d_{2k4}, w2_{2k4}, d, w2)
    __shared__ float  vals[4][NB];
    __shared__ float  msqs[4];
    int bid = blockIdx.x, tid = threadIdx.x;
    int warp = tid >> 5, lane = tid & 31;
    int t0 = bid * 4;

    // load W (L2-hot, 16KB) and scales
#pragma unroll
    for (int e = 0; e < 16; e++) wsm[tid + 256 * e] = g_Wg[tid + 256 * e];
    if (tid < 63) scs[tid] = ALPHA_8 * rsqrtf(fmaxf(g_poles[tid + 1], 1e-20f));

    float mv[4];
#pragma unroll
    for (int q = 0; q < 4; q++) {
        mv[q] = g_M[(t0 + q) * D_ + tid];
        smv[q][tid] = mv[q];
    }
#pragma unroll
    for (int q = 0; q < 4; q++) {
        float p = mv[q] * mv[q];
#pragma unroll
        for (int o = 16; o > 0; o >>= 1)
            p += __shfl_down_sync(0xFFFFFFFFu, p, o);
        if (lane == 0) redp[q][warp] = p;
    }
    __syncthreads();

    // y_i = D0_i . m  (warp-per-row; D0 row loaded once, reused for 4 t's)
#pragma unroll
    for (int it = 0; it < 8; it++) {
        int i = warp * 8 + it;
        float a0 = 0.f, a1 = 0.f, a2 = 0.f, a3 = 0.f;
#pragma unroll
        for (int j = 0; j < 8; j++) {
            int d = lane + 32 * j;
            float u = __ldg(&g_D0[i * D_ + d]);
            a0 += u * smv[0][d];
            a1 += u * smv[1][d];
            a2 += u * smv[2][d];
            a3 += u * smv[3][d];
        }
#pragma unroll
        for (int o = 16; o > 0; o >>= 1) {
            a0 += __shfl_down_sync(0xFFFFFFFFu, a0, o);
            a1 += __shfl_down_sync(0xFFFFFFFFu, a1, o);
            a2 += __shfl_down_sync(0xFFFFFFFFu, a2, o);
            a3 += __shfl_down_sync(0xFFFFFFFFu, a3, o);
        }
        if (lane == 0) {
            ysh[0][i] = a0; ysh[1][i] = a1;
            ysh[2][i] = a2; ysh[3][i] = a3;
        }
    }
    __syncthreads();

    // z_k = scale_k * sum_i W[i][k+1] * y_i   (thread (sel,k), k<63)
    {
        int sel = tid >> 6, k = tid & 63;
        if (k < 63) {
            float a0 = 0.f, a1 = 0.f;
#pragma unroll
            for (int i = 0; i < NB; i += 2) {
                a0 += wsm[i * 64 + k + 1]       * ysh[sel][i];
                a1 += wsm[(i + 1) * 64 + k + 1] * ysh[sel][i + 1];
            }
            zsh[sel][k] = scs[k] * (a0 + a1);
        }
    }
    __syncthreads();

    // weights: thread (sel*64 + i) fills (pole_i, w2_i) slot
    {
        int sel = tid >> 6, i = tid & 63;
        float* dwf = (float*)dw4[sel];
        if (i == 0) {
            float msq = 0.f;
#pragma unroll
            for (int w = 0; w < 8; w++) msq += redp[sel][w];
            float sz = 0.f;
            for (int k = 0; k < 63; k++) sz += zsh[sel][k] * zsh[sel][k];
            dwf[0] = g_poles[0];
            dwf[1] = fmaxf(msq - sz, 0.f);
            msqs[sel] = msq;
        } else {
            float z = zsh[sel][i - 1];
            dwf[2 * i]     = g_poles[i];
            dwf[2 * i + 1] = z * z;
        }
    }
    __syncthreads();

    int sel = tid >> 6, i = tid & 63;
    const float* dwf = (const float*)dw4[sel];
    float S = msqs[sel];              // Sum w2 == msq algebraically

    float lo = dwf[2 * i];
    float hi = (i < 63) ? dwf[2 * i + 2] : dwf[126] + S;
    float lam = 0.5f * (lo + hi);

    for (int it = 0; it < NIT; it++) {
        float f = 1.f, fp = 0.f;
#pragma unroll 8
        for (int k4 = 0; k4 < 32; k4++) {
            float4 q = dw4[sel][k4];
            float r0, r1;
            asm("rcp.approx.f32 %0, %1;" : "=f"(r0) : "f"(q.x - lam));
            float t0v = q.y * r0;
            f  += t0v;
            fp += t0v * r0;
            asm("rcp.approx.f32 %0, %1;" : "=f"(r1) : "f"(q.z - lam));
            float t1v = q.w * r1;
            f  += t1v;
            fp += t1v * r1;
        }
        if (f > 0.f) hi = lam; else lo = lam;
        float ln = lam - __fdividef(f, fp);
        lam = (ln > lo && ln < hi) ? ln : 0.5f * (lo + hi);
    }

    float tr = msqs[sel] + g_trA;
    float v = fmaxf(__fdividef(lam, tr), EPSV);
    vals[sel][i] = v;
    __syncthreads();

    float ssum = 192.f * EPSV;
#pragma unroll 8
    for (int k = 0; k < NB; k++) ssum += vals[sel][k];
    float inv = __frcp_rn(ssum);

    float* o = out + (long)(t0 + sel) * D_;
    float ev = EPSV * inv;
    o[i]        = ev;               // positions   0..63  (zero eigs)
    o[i + 64]   = ev;               // positions  64..127
    o[i + 128]  = ev;               // positions 128..191
    o[i + 192]  = vals[sel][i] * inv;  // positions 192..255 (roots, ascending)
}

// ---------------- launcher ----------------
extern "C" void kernel_launch(void* const* d_in, const int* in_sizes, int n_in,
                              void* d_out, int out_size) {
    const int*   tokens = (const int*)d_in[0];
    const float* embed  = (const float*)d_in[1];
    const float* bubbles= (const float*)d_in[2];
    const float* mdecay = (const float*)d_in[3];
    float* out = (float*)d_out;

    cudaFuncSetAttribute(k_eigvec, cudaFuncAttributeMaxDynamicSharedMemorySize,
                         66560);

    k_scan_gram<<<96, 256>>>(tokens, embed, bubbles, mdecay);
    k_tridiag  <<<1, 64>>>();
    k_eigvec   <<<1, 1024, 66560>>>();
    k_wsec     <<<256, 256>>>(out);
    (void)in_sizes; (void)n_in; (void)out_size;
}